// round 5
// baseline (speedup 1.0000x reference)
#include <cuda_runtime.h>
#include <cuda_bf16.h>
#include <cstdint>
#include <cstddef>

#define NN 100000
#define EE 1600000
#define DD 128

// ---------------- scratch (device globals; no allocation allowed) ----------
__device__ float  g_agg[(size_t)NN * DD];
__device__ float  g_h1[(size_t)NN * DD];
__device__ float  g_h2[(size_t)NN * DD];
__device__ float  g_inv[NN];
__device__ unsigned short g_Bh[3][128 * 256];
__device__ unsigned short g_Bl[3][128 * 256];
__device__ int    g_deg[NN];
__device__ int    g_rowptr[NN + 1];
__device__ int    g_cursor[NN];
__device__ int    g_col[EE];
__device__ int    g_bsums[256];
__device__ int    g_is64;

// ---------------- int64/int32 edge-index detection -------------------------
__global__ void detect_idx_kernel(const void* ei, int e, int n) {
    if (threadIdx.x != 0 || blockIdx.x != 0) return;
    const long long* p = (const long long*)ei;
    int is64 = 1;
    int lim = (e < 256) ? e : 256;
    for (int i = 0; i < lim; i++) {
        long long v = p[i];
        if (v < 0 || v >= n) { is64 = 0; break; }
    }
    g_is64 = is64;
}

__device__ __forceinline__ int load_idx(const void* ei, int e, int i, int part, int is64) {
    if (is64) return (int)(((const long long*)ei)[(size_t)part * e + i]);
    return ((const int*)ei)[(size_t)part * e + i];
}

// ---------------- CSR construction ------------------------------------------
__global__ void hist_kernel(const void* __restrict__ ei, int e, int* __restrict__ deg) {
    int i = blockIdx.x * blockDim.x + threadIdx.x;
    if (i >= e) return;
    int dst = load_idx(ei, e, i, 1, g_is64);
    atomicAdd(&deg[dst], 1);
}

__global__ void scanA_kernel(const int* __restrict__ deg, int* __restrict__ rp,
                             int* __restrict__ bsums, int n) {
    __shared__ int wsum[8];
    int t = threadIdx.x;
    int base = blockIdx.x * 1024;
    int idx = base + t * 4;
    int v[4];
    #pragma unroll
    for (int j = 0; j < 4; j++) v[j] = (idx + j < n) ? deg[idx + j] : 0;
    int tsum = v[0] + v[1] + v[2] + v[3];
    int lane = t & 31, w = t >> 5;
    int inc = tsum;
    #pragma unroll
    for (int d = 1; d < 32; d <<= 1) {
        int x = __shfl_up_sync(0xFFFFFFFFu, inc, d);
        if (lane >= d) inc += x;
    }
    if (lane == 31) wsum[w] = inc;
    __syncthreads();
    if (t == 0) {
        int a = 0;
        #pragma unroll
        for (int i = 0; i < 8; i++) { int tmp = wsum[i]; wsum[i] = a; a += tmp; }
        bsums[blockIdx.x] = a;
    }
    __syncthreads();
    int run = inc - tsum + wsum[w];
    #pragma unroll
    for (int j = 0; j < 4; j++) {
        if (idx + j < n) rp[idx + j] = run;
        run += v[j];
    }
}

__global__ void scanB_kernel(int* __restrict__ bsums, int nb) {
    __shared__ int sh[256];
    int t = threadIdx.x;
    sh[t] = (t < nb) ? bsums[t] : 0;
    __syncthreads();
    if (t == 0) {
        int a = 0;
        for (int i = 0; i < nb; i++) { int tmp = sh[i]; sh[i] = a; a += tmp; }
    }
    __syncthreads();
    if (t < nb) bsums[t] = sh[t];
}

__global__ void scanC_kernel(int* __restrict__ rp, int* __restrict__ cursor,
                             const int* __restrict__ bsums, const int* __restrict__ deg,
                             float* __restrict__ inv, int n, int e) {
    int i = blockIdx.x * blockDim.x + threadIdx.x;
    if (i >= n) return;
    int v = rp[i] + bsums[i >> 10];
    rp[i] = v;
    cursor[i] = v;
    inv[i] = 1.0f / fmaxf((float)deg[i], 1.0f);
    if (i == 0) rp[n] = e;
}

__global__ void fill_kernel(const void* __restrict__ ei, int e,
                            int* __restrict__ cursor, int* __restrict__ col) {
    int i = blockIdx.x * blockDim.x + threadIdx.x;
    if (i >= e) return;
    int is64 = g_is64;
    int src = load_idx(ei, e, i, 0, is64);
    int dst = load_idx(ei, e, i, 1, is64);
    int pos = atomicAdd(&cursor[dst], 1);
    col[pos] = src;
}

// ---------------- weights -> bf16 hi/lo, K-major B[j][k] --------------------
__global__ void build_wb_kernel(const float* __restrict__ Wl, const float* __restrict__ Wr,
                                unsigned short* __restrict__ Bh, unsigned short* __restrict__ Bl) {
    int j = blockIdx.x;       // 0..127 output col
    int k = threadIdx.x;      // 0..255
    float w = (k < DD) ? Wl[j * DD + k] : Wr[j * DD + (k - DD)];
    __nv_bfloat16 h = __float2bfloat16_rn(w);
    float lo = w - __bfloat162float(h);
    __nv_bfloat16 l = __float2bfloat16_rn(lo);
    Bh[j * 256 + k] = __bfloat16_as_ushort(h);
    Bl[j * 256 + k] = __bfloat16_as_ushort(l);
}

// ---------------- CSR gather mean: one warp per node ------------------------
__global__ __launch_bounds__(256) void gather_kernel(
    const float* __restrict__ xin, const int* __restrict__ rp,
    const int* __restrict__ col, const float* __restrict__ inv,
    float* __restrict__ agg, int n)
{
    int node = (blockIdx.x * blockDim.x + threadIdx.x) >> 5;
    int lane = threadIdx.x & 31;
    if (node >= n) return;
    int beg = rp[node], end = rp[node + 1];
    const float4* xv = (const float4*)xin;
    float4 acc = make_float4(0.f, 0.f, 0.f, 0.f);
    int j = beg;
    for (; j + 4 <= end; j += 4) {
        int s0 = __ldg(&col[j + 0]);
        int s1 = __ldg(&col[j + 1]);
        int s2 = __ldg(&col[j + 2]);
        int s3 = __ldg(&col[j + 3]);
        float4 v0 = __ldg(&xv[(size_t)s0 * 32 + lane]);
        float4 v1 = __ldg(&xv[(size_t)s1 * 32 + lane]);
        float4 v2 = __ldg(&xv[(size_t)s2 * 32 + lane]);
        float4 v3 = __ldg(&xv[(size_t)s3 * 32 + lane]);
        acc.x += v0.x + v1.x + v2.x + v3.x;
        acc.y += v0.y + v1.y + v2.y + v3.y;
        acc.z += v0.z + v1.z + v2.z + v3.z;
        acc.w += v0.w + v1.w + v2.w + v3.w;
    }
    for (; j < end; j++) {
        int s = __ldg(&col[j]);
        float4 v = __ldg(&xv[(size_t)s * 32 + lane]);
        acc.x += v.x; acc.y += v.y; acc.z += v.z; acc.w += v.w;
    }
    float sc = inv[node];
    acc.x *= sc; acc.y *= sc; acc.z *= sc; acc.w *= sc;
    ((float4*)agg)[(size_t)node * 32 + lane] = acc;
}

// ---------------- split-bf16 HMMA GEMM (mma.sync, baseline PTX) -------------
// out[m][j] = sum_k A[m][k]*B[j][k] + bias[j];  A=[mean|xin] fp32 split to
// bf16 hi/lo on the fly; 3 passes hi*hi + hi*lo + lo*hi into fp32 accum.
// CTA: 128x128 tile, K=256 in 4 chunks of 64. 8 warps = 4(m) x 2(n) of 32x64.

#define AS 72     // A smem stride (bf16) -> conflict-free fragment LDS
#define BS 264    // B smem stride (bf16)

#define SM_BIAS 0
#define SM_B_HI 512
#define SM_B_LO (SM_B_HI + 67584)
#define SM_A    (SM_B_LO + 67584)
#define SM_ABUF 36864
#define SM_TOTAL (SM_A + 2 * SM_ABUF)

__device__ __forceinline__ void mma16816(float* d, const uint32_t* a,
                                         uint32_t b0, uint32_t b1) {
    asm volatile("mma.sync.aligned.m16n8k16.row.col.f32.bf16.bf16.f32 "
                 "{%0,%1,%2,%3}, {%4,%5,%6,%7}, {%8,%9}, {%0,%1,%2,%3};"
                 : "+f"(d[0]), "+f"(d[1]), "+f"(d[2]), "+f"(d[3])
                 : "r"(a[0]), "r"(a[1]), "r"(a[2]), "r"(a[3]), "r"(b0), "r"(b1));
}

__global__ __launch_bounds__(256) void gemm_hmma_kernel(
    const float* __restrict__ mean, const float* __restrict__ xin,
    const unsigned short* __restrict__ Bh, const unsigned short* __restrict__ Bl,
    const float* __restrict__ bias, float* __restrict__ out,
    int n, int do_relu)
{
    extern __shared__ char smem[];
    float* bsh = (float*)(smem + SM_BIAS);
    unsigned short* bh_s = (unsigned short*)(smem + SM_B_HI);
    unsigned short* bl_s = (unsigned short*)(smem + SM_B_LO);

    const int tid  = threadIdx.x;
    const int lane = tid & 31;
    const int wid  = tid >> 5;
    const int brow = blockIdx.x * 128;
    const int row  = tid >> 1;        // loader row 0..127
    const int half = tid & 1;         // loader k-half

    if (tid < 128) bsh[tid] = bias[tid];
    // B copy (128 x 256 bf16, hi+lo) into padded smem
    {
        const uint2* srch = (const uint2*)(Bh + row * 256 + half * 128);
        const uint2* srcl = (const uint2*)(Bl + row * 256 + half * 128);
        uint2* dsth = (uint2*)(bh_s + row * BS + half * 128);
        uint2* dstl = (uint2*)(bl_s + row * BS + half * 128);
        #pragma unroll
        for (int i = 0; i < 32; i++) { dsth[i] = srch[i]; dstl[i] = srcl[i]; }
    }

    const int grow = brow + row;
    const bool rok = (grow < n);

    float acc[2][8][4];
    #pragma unroll
    for (int mi = 0; mi < 2; mi++)
        #pragma unroll
        for (int ni = 0; ni < 8; ni++)
            #pragma unroll
            for (int q = 0; q < 4; q++) acc[mi][ni][q] = 0.0f;

    const int m0 = (wid & 3) * 32;
    const int n0 = (wid >> 2) * 64;
    const int g  = lane >> 2;
    const int c2 = (lane & 3) * 2;

    float4 v[8];
    // fetch chunk c of A rows into regs
    auto fetchA = [&](int c) {
        const float* basep = (c < 2) ? mean : xin;
        const float* s = basep + (size_t)grow * DD + (c & 1) * 64 + half * 32;
        #pragma unroll
        for (int j = 0; j < 8; j++)
            v[j] = rok ? *(const float4*)(s + j * 4) : make_float4(0.f, 0.f, 0.f, 0.f);
    };
    // split regs -> smem buf (hi & lo)
    auto storeA = [&](int buf) {
        unsigned short* ah = (unsigned short*)(smem + SM_A + buf * SM_ABUF);
        unsigned short* al = ah + 9216;
        #pragma unroll
        for (int j = 0; j < 8; j++) {
            __nv_bfloat16 h0 = __float2bfloat16_rn(v[j].x);
            __nv_bfloat16 h1 = __float2bfloat16_rn(v[j].y);
            __nv_bfloat16 h2 = __float2bfloat16_rn(v[j].z);
            __nv_bfloat16 h3 = __float2bfloat16_rn(v[j].w);
            __nv_bfloat16 l0 = __float2bfloat16_rn(v[j].x - __bfloat162float(h0));
            __nv_bfloat16 l1 = __float2bfloat16_rn(v[j].y - __bfloat162float(h1));
            __nv_bfloat16 l2 = __float2bfloat16_rn(v[j].z - __bfloat162float(h2));
            __nv_bfloat16 l3 = __float2bfloat16_rn(v[j].w - __bfloat162float(h3));
            uint2 hv, lv;
            hv.x = (uint32_t)__bfloat16_as_ushort(h0) | ((uint32_t)__bfloat16_as_ushort(h1) << 16);
            hv.y = (uint32_t)__bfloat16_as_ushort(h2) | ((uint32_t)__bfloat16_as_ushort(h3) << 16);
            lv.x = (uint32_t)__bfloat16_as_ushort(l0) | ((uint32_t)__bfloat16_as_ushort(l1) << 16);
            lv.y = (uint32_t)__bfloat16_as_ushort(l2) | ((uint32_t)__bfloat16_as_ushort(l3) << 16);
            int idx = row * AS + half * 32 + j * 4;
            *(uint2*)(ah + idx) = hv;
            *(uint2*)(al + idx) = lv;
        }
    };
    // MMA over one 64-wide chunk resident in buf
    auto compute = [&](int c, int buf) {
        const unsigned short* ah = (const unsigned short*)(smem + SM_A + buf * SM_ABUF);
        const unsigned short* al = ah + 9216;
        const int kg = c * 64;
        #pragma unroll
        for (int ks = 0; ks < 4; ks++) {
            const int k0 = ks * 16;
            uint32_t ahi[2][4], alo[2][4];
            #pragma unroll
            for (int mi = 0; mi < 2; mi++) {
                int mb = m0 + mi * 16;
                ahi[mi][0] = *(const uint32_t*)&ah[(mb + g) * AS + k0 + c2];
                ahi[mi][1] = *(const uint32_t*)&ah[(mb + 8 + g) * AS + k0 + c2];
                ahi[mi][2] = *(const uint32_t*)&ah[(mb + g) * AS + k0 + 8 + c2];
                ahi[mi][3] = *(const uint32_t*)&ah[(mb + 8 + g) * AS + k0 + 8 + c2];
                alo[mi][0] = *(const uint32_t*)&al[(mb + g) * AS + k0 + c2];
                alo[mi][1] = *(const uint32_t*)&al[(mb + 8 + g) * AS + k0 + c2];
                alo[mi][2] = *(const uint32_t*)&al[(mb + g) * AS + k0 + 8 + c2];
                alo[mi][3] = *(const uint32_t*)&al[(mb + 8 + g) * AS + k0 + 8 + c2];
            }
            #pragma unroll
            for (int ni = 0; ni < 8; ni++) {
                int nb = n0 + ni * 8;
                uint32_t bh0 = *(const uint32_t*)&bh_s[(nb + g) * BS + kg + k0 + c2];
                uint32_t bh1 = *(const uint32_t*)&bh_s[(nb + g) * BS + kg + k0 + 8 + c2];
                uint32_t bl0 = *(const uint32_t*)&bl_s[(nb + g) * BS + kg + k0 + c2];
                uint32_t bl1 = *(const uint32_t*)&bl_s[(nb + g) * BS + kg + k0 + 8 + c2];
                #pragma unroll
                for (int mi = 0; mi < 2; mi++) {
                    mma16816(acc[mi][ni], ahi[mi], bh0, bh1);
                    mma16816(acc[mi][ni], ahi[mi], bl0, bl1);
                    mma16816(acc[mi][ni], alo[mi], bh0, bh1);
                }
            }
        }
    };

    fetchA(0);
    storeA(0);
    __syncthreads();
    #pragma unroll
    for (int c = 0; c < 4; c++) {
        if (c < 3) fetchA(c + 1);          // gmem prefetch overlaps MMA below
        compute(c, c & 1);
        if (c < 3) storeA((c + 1) & 1);
        __syncthreads();
    }

    // epilogue: bias + relu, direct to gmem
    #pragma unroll
    for (int mi = 0; mi < 2; mi++) {
        int r0 = brow + m0 + mi * 16 + g;
        #pragma unroll
        for (int ni = 0; ni < 8; ni++) {
            int colx = n0 + ni * 8 + c2;
            float bb0 = bsh[colx], bb1 = bsh[colx + 1];
            if (r0 < n) {
                float2 o = make_float2(acc[mi][ni][0] + bb0, acc[mi][ni][1] + bb1);
                if (do_relu) { o.x = fmaxf(o.x, 0.f); o.y = fmaxf(o.y, 0.f); }
                *(float2*)(out + (size_t)r0 * DD + colx) = o;
            }
            if (r0 + 8 < n) {
                float2 o = make_float2(acc[mi][ni][2] + bb0, acc[mi][ni][3] + bb1);
                if (do_relu) { o.x = fmaxf(o.x, 0.f); o.y = fmaxf(o.y, 0.f); }
                *(float2*)(out + (size_t)(r0 + 8) * DD + colx) = o;
            }
        }
    }
}

// ---------------- host orchestration ---------------------------------------
extern "C" void kernel_launch(void* const* d_in, const int* in_sizes, int n_in,
                              void* d_out, int out_size) {
    const float* x   = (const float*)d_in[0];
    const void*  ei  = d_in[1];
    const float* Wl1 = (const float*)d_in[2];
    const float* Wr1 = (const float*)d_in[3];
    const float* b1  = (const float*)d_in[4];
    const float* Wl2 = (const float*)d_in[5];
    const float* Wr2 = (const float*)d_in[6];
    const float* b2  = (const float*)d_in[7];
    const float* Wl3 = (const float*)d_in[8];
    const float* Wr3 = (const float*)d_in[9];
    const float* b3  = (const float*)d_in[10];

    const int n = in_sizes[0] / DD;
    const int e = in_sizes[1] / 2;
    float* out = (float*)d_out;

    float *agg, *h1, *h2, *inv;
    unsigned short *bh, *bl;
    int *deg, *rp, *cursor, *col, *bsums;
    cudaGetSymbolAddress((void**)&agg,    g_agg);
    cudaGetSymbolAddress((void**)&h1,     g_h1);
    cudaGetSymbolAddress((void**)&h2,     g_h2);
    cudaGetSymbolAddress((void**)&inv,    g_inv);
    cudaGetSymbolAddress((void**)&bh,     g_Bh);
    cudaGetSymbolAddress((void**)&bl,     g_Bl);
    cudaGetSymbolAddress((void**)&deg,    g_deg);
    cudaGetSymbolAddress((void**)&rp,     g_rowptr);
    cudaGetSymbolAddress((void**)&cursor, g_cursor);
    cudaGetSymbolAddress((void**)&col,    g_col);
    cudaGetSymbolAddress((void**)&bsums,  g_bsums);

    cudaFuncSetAttribute(gemm_hmma_kernel,
                         cudaFuncAttributeMaxDynamicSharedMemorySize, SM_TOTAL);

    const int thr = 256;
    const int eb   = (e + thr - 1) / thr;
    const int nb   = (n + thr - 1) / thr;
    const int scb  = (n + 1023) / 1024;
    const int gab  = (n * 32 + thr - 1) / thr;
    const int gemb = (n + 127) / 128;

    // --- CSR build ---
    detect_idx_kernel<<<1, 1>>>(ei, e, n);
    cudaMemsetAsync(deg, 0, (size_t)n * sizeof(int));
    hist_kernel<<<eb, thr>>>(ei, e, deg);
    scanA_kernel<<<scb, 256>>>(deg, rp, bsums, n);
    scanB_kernel<<<1, 256>>>(bsums, scb);
    scanC_kernel<<<nb, thr>>>(rp, cursor, bsums, deg, inv, n, e);
    fill_kernel<<<eb, thr>>>(ei, e, cursor, col);

    build_wb_kernel<<<128, 256>>>(Wl1, Wr1, bh + 0 * 128 * 256, bl + 0 * 128 * 256);
    build_wb_kernel<<<128, 256>>>(Wl2, Wr2, bh + 1 * 128 * 256, bl + 1 * 128 * 256);
    build_wb_kernel<<<128, 256>>>(Wl3, Wr3, bh + 2 * 128 * 256, bl + 2 * 128 * 256);

    // --- layer 1 ---
    gather_kernel<<<gab, thr>>>(x, rp, col, inv, agg, n);
    gemm_hmma_kernel<<<gemb, 256, SM_TOTAL>>>(agg, x, bh + 0 * 128 * 256, bl + 0 * 128 * 256, b1, h1, n, 1);
    // --- layer 2 ---
    gather_kernel<<<gab, thr>>>(h1, rp, col, inv, agg, n);
    gemm_hmma_kernel<<<gemb, 256, SM_TOTAL>>>(agg, h1, bh + 1 * 128 * 256, bl + 1 * 128 * 256, b2, h2, n, 1);
    // --- layer 3 ---
    gather_kernel<<<gab, thr>>>(h2, rp, col, inv, agg, n);
    gemm_hmma_kernel<<<gemb, 256, SM_TOTAL>>>(agg, h2, bh + 2 * 128 * 256, bl + 2 * 128 * 256, b3, out, n, 0);
}

// round 9
// speedup vs baseline: 1.2928x; 1.2928x over previous
#include <cuda_runtime.h>
#include <cuda_bf16.h>
#include <cstdint>
#include <cstddef>

#define NN 100000
#define EE 1600000
#define DD 128

typedef unsigned short ushort_t;

// ---------------- scratch (device globals; no allocation allowed) ----------
__device__ ushort_t g_xh[(size_t)NN * DD];
__device__ ushort_t g_xl[(size_t)NN * DD];
__device__ ushort_t g_h1h[(size_t)NN * DD];
__device__ ushort_t g_h1l[(size_t)NN * DD];
__device__ ushort_t g_h2h[(size_t)NN * DD];
__device__ ushort_t g_h2l[(size_t)NN * DD];
__device__ ushort_t g_aggh[(size_t)NN * DD];
__device__ ushort_t g_aggl[(size_t)NN * DD];
__device__ float    g_inv[NN];
__device__ __align__(16) ushort_t g_Bh[3][128 * 256];
__device__ __align__(16) ushort_t g_Bl[3][128 * 256];
__device__ int      g_deg[NN];
__device__ int      g_rps[NN];
__device__ int      g_rpe[NN];
__device__ int      g_cursor[NN];
__device__ int      g_col[EE];
__device__ int      g_ecur;

// ---------------- PTX helpers ----------------------------------------------
__device__ __forceinline__ uint32_t smem_u32(const void* p) {
    uint32_t a;
    asm("{ .reg .u64 t; cvta.to.shared.u64 t, %1; cvt.u32.u64 %0, t; }" : "=r"(a) : "l"(p));
    return a;
}
__device__ __forceinline__ void cp16(uint32_t dst, const void* src, bool ok) {
    int sz = ok ? 16 : 0;
    asm volatile("cp.async.cg.shared.global [%0], [%1], 16, %2;"
                 :: "r"(dst), "l"(src), "r"(sz));
}
__device__ __forceinline__ void cp_commit() {
    asm volatile("cp.async.commit_group;" ::: "memory");
}
template <int N>
__device__ __forceinline__ void cp_wait() {
    asm volatile("cp.async.wait_group %0;" :: "n"(N) : "memory");
}
__device__ __forceinline__ void ldsm4(uint32_t* r, uint32_t addr) {
    asm volatile("ldmatrix.sync.aligned.m8n8.x4.shared.b16 {%0,%1,%2,%3}, [%4];"
                 : "=r"(r[0]), "=r"(r[1]), "=r"(r[2]), "=r"(r[3]) : "r"(addr));
}
__device__ __forceinline__ void mma16816(float* d, const uint32_t* a,
                                         uint32_t b0, uint32_t b1) {
    asm volatile("mma.sync.aligned.m16n8k16.row.col.f32.bf16.bf16.f32 "
                 "{%0,%1,%2,%3}, {%4,%5,%6,%7}, {%8,%9}, {%0,%1,%2,%3};"
                 : "+f"(d[0]), "+f"(d[1]), "+f"(d[2]), "+f"(d[3])
                 : "r"(a[0]), "r"(a[1]), "r"(a[2]), "r"(a[3]), "r"(b0), "r"(b1));
}
// A smem: 128 rows x 128B (64 bf16); B smem: 128 rows x 512B (256 bf16)
__device__ __forceinline__ uint32_t ASWZ(int row, int kbyte) {
    return (uint32_t)(row * 128 + ((((kbyte >> 4) ^ (row & 7)) << 4) | (kbyte & 15)));
}
__device__ __forceinline__ uint32_t BSWZ(int row, int kbyte) {
    return (uint32_t)(row * 512 + (((((kbyte >> 4) & 7) ^ (row & 7)) << 4) |
                                   ((kbyte >> 4) & ~7) * 16 + (kbyte & 15)));
}

// per-block int64/int32 detection (warp 0 vote)
__device__ __forceinline__ int detect_is64(const void* ei, int e, int n, int* s_flag) {
    if (threadIdx.x < 32) {
        int ok = 1;
        int lim = (e < 256) ? e : 256;
        for (int q = threadIdx.x; q < lim; q += 32) {
            long long v = ((const long long*)ei)[q];
            if (v < 0 || v >= n) ok = 0;
        }
        int all = __all_sync(0xFFFFFFFFu, ok);
        if (threadIdx.x == 0) *s_flag = all;
    }
    __syncthreads();
    return *s_flag;
}
__device__ __forceinline__ int load_idx(const void* ei, int e, int i, int part, int is64) {
    if (is64) return (int)(((const long long*)ei)[(size_t)part * e + i]);
    return ((const int*)ei)[(size_t)part * e + i];
}

// ---------------- hist + x->bf16 hi/lo conversion ---------------------------
__global__ __launch_bounds__(256) void hist_conv_kernel(
    const void* __restrict__ ei, int e, int* __restrict__ deg,
    const float* __restrict__ x, ushort_t* __restrict__ xh, ushort_t* __restrict__ xl,
    int n)
{
    __shared__ int s64;
    int is64 = detect_is64(ei, e, n, &s64);
    int gid = blockIdx.x * blockDim.x + threadIdx.x;
    if (gid < e) {
        int dst = load_idx(ei, e, gid, 1, is64);
        atomicAdd(&deg[dst], 1);
    }
    size_t total = (size_t)n * DD;
    size_t stride = (size_t)gridDim.x * blockDim.x * 8;
    for (size_t j = (size_t)gid * 8; j + 7 < total; j += stride) {
        float4 p0 = *(const float4*)(x + j);
        float4 p1 = *(const float4*)(x + j + 4);
        float vv[8] = {p0.x, p0.y, p0.z, p0.w, p1.x, p1.y, p1.z, p1.w};
        ushort_t hh[8], ll[8];
        #pragma unroll
        for (int q = 0; q < 8; q++) {
            __nv_bfloat16 h = __float2bfloat16_rn(vv[q]);
            __nv_bfloat16 l = __float2bfloat16_rn(vv[q] - __bfloat162float(h));
            hh[q] = __bfloat16_as_ushort(h);
            ll[q] = __bfloat16_as_ushort(l);
        }
        *(uint4*)(xh + j) = *(uint4*)hh;
        *(uint4*)(xl + j) = *(uint4*)ll;
    }
}

// ---------------- segment assignment (block scan + atomic base) + wb build --
__global__ __launch_bounds__(256) void seg_kernel(
    const int* __restrict__ deg, int* __restrict__ rps, int* __restrict__ rpe,
    int* __restrict__ cursor, float* __restrict__ inv, int n, int scan_blocks,
    const float* __restrict__ Wl1, const float* __restrict__ Wr1,
    const float* __restrict__ Wl2, const float* __restrict__ Wr2,
    const float* __restrict__ Wl3, const float* __restrict__ Wr3,
    ushort_t* __restrict__ Bh, ushort_t* __restrict__ Bl)
{
    if ((int)blockIdx.x >= scan_blocks) {
        int layer = blockIdx.x - scan_blocks;
        const float* Wl = (layer == 0) ? Wl1 : (layer == 1) ? Wl2 : Wl3;
        const float* Wr = (layer == 0) ? Wr1 : (layer == 1) ? Wr2 : Wr3;
        ushort_t* bh = Bh + layer * 128 * 256;
        ushort_t* bl = Bl + layer * 128 * 256;
        for (int idx = threadIdx.x; idx < 128 * 256; idx += 256) {
            int j = idx >> 8, k = idx & 255;
            float w = (k < DD) ? Wl[j * DD + k] : Wr[j * DD + (k - DD)];
            __nv_bfloat16 h = __float2bfloat16_rn(w);
            __nv_bfloat16 l = __float2bfloat16_rn(w - __bfloat162float(h));
            bh[idx] = __bfloat16_as_ushort(h);
            bl[idx] = __bfloat16_as_ushort(l);
        }
        return;
    }
    __shared__ int wsum[8];
    __shared__ int sbase;
    int t = threadIdx.x;
    int base = blockIdx.x * 1024;
    int idx = base + t * 4;
    int v[4];
    #pragma unroll
    for (int j = 0; j < 4; j++) v[j] = (idx + j < n) ? deg[idx + j] : 0;
    int tsum = v[0] + v[1] + v[2] + v[3];
    int lane = t & 31, w = t >> 5;
    int inc = tsum;
    #pragma unroll
    for (int d = 1; d < 32; d <<= 1) {
        int x2 = __shfl_up_sync(0xFFFFFFFFu, inc, d);
        if (lane >= d) inc += x2;
    }
    if (lane == 31) wsum[w] = inc;
    __syncthreads();
    if (t == 0) {
        int a = 0;
        #pragma unroll
        for (int i = 0; i < 8; i++) { int tmp = wsum[i]; wsum[i] = a; a += tmp; }
        sbase = atomicAdd(&g_ecur, a);
    }
    __syncthreads();
    int run = sbase + wsum[w] + (inc - tsum);
    #pragma unroll
    for (int j = 0; j < 4; j++) {
        if (idx + j < n) {
            rps[idx + j] = run;
            rpe[idx + j] = run + v[j];
            cursor[idx + j] = run;
            inv[idx + j] = 1.0f / fmaxf((float)v[j], 1.0f);
        }
        run += v[j];
    }
}

// ---------------- fill ------------------------------------------------------
__global__ __launch_bounds__(256) void fill_kernel(
    const void* __restrict__ ei, int e, int n,
    int* __restrict__ cursor, int* __restrict__ col)
{
    __shared__ int s64;
    int is64 = detect_is64(ei, e, n, &s64);
    int i = blockIdx.x * blockDim.x + threadIdx.x;
    if (i >= e) return;
    int src = load_idx(ei, e, i, 0, is64);
    int dst = load_idx(ei, e, i, 1, is64);
    int pos = atomicAdd(&cursor[dst], 1);
    col[pos] = src;
}

// ---------------- gather mean (bf16 hi/lo in, bf16 hi/lo out) ---------------
__global__ __launch_bounds__(256) void gather_kernel(
    const ushort_t* __restrict__ xh, const ushort_t* __restrict__ xl,
    const int* __restrict__ rps, const int* __restrict__ rpe,
    const int* __restrict__ col, const float* __restrict__ inv,
    ushort_t* __restrict__ aggh, ushort_t* __restrict__ aggl, int n)
{
    int node = (blockIdx.x * blockDim.x + threadIdx.x) >> 5;
    int lane = threadIdx.x & 31;
    if (node >= n) return;
    int beg = rps[node], end = rpe[node];
    float a0 = 0.f, a1 = 0.f, a2 = 0.f, a3 = 0.f;
    const size_t lo4 = (size_t)lane * 4;
    for (int j = beg; j < end; j++) {
        int s = __ldg(&col[j]);
        uint2 hv = __ldg((const uint2*)(xh + (size_t)s * DD + lo4));
        uint2 lv = __ldg((const uint2*)(xl + (size_t)s * DD + lo4));
        float2 h0 = __bfloat1622float2(*reinterpret_cast<__nv_bfloat162*>(&hv.x));
        float2 h1 = __bfloat1622float2(*reinterpret_cast<__nv_bfloat162*>(&hv.y));
        float2 l0 = __bfloat1622float2(*reinterpret_cast<__nv_bfloat162*>(&lv.x));
        float2 l1 = __bfloat1622float2(*reinterpret_cast<__nv_bfloat162*>(&lv.y));
        a0 += h0.x + l0.x;
        a1 += h0.y + l0.y;
        a2 += h1.x + l1.x;
        a3 += h1.y + l1.y;
    }
    float sc = inv[node];
    a0 *= sc; a1 *= sc; a2 *= sc; a3 *= sc;
    __nv_bfloat16 h0 = __float2bfloat16_rn(a0);
    __nv_bfloat16 h1 = __float2bfloat16_rn(a1);
    __nv_bfloat16 h2 = __float2bfloat16_rn(a2);
    __nv_bfloat16 h3 = __float2bfloat16_rn(a3);
    __nv_bfloat16 l0 = __float2bfloat16_rn(a0 - __bfloat162float(h0));
    __nv_bfloat16 l1 = __float2bfloat16_rn(a1 - __bfloat162float(h1));
    __nv_bfloat16 l2 = __float2bfloat16_rn(a2 - __bfloat162float(h2));
    __nv_bfloat16 l3 = __float2bfloat16_rn(a3 - __bfloat162float(h3));
    uint2 hv, lv;
    hv.x = (uint32_t)__bfloat16_as_ushort(h0) | ((uint32_t)__bfloat16_as_ushort(h1) << 16);
    hv.y = (uint32_t)__bfloat16_as_ushort(h2) | ((uint32_t)__bfloat16_as_ushort(h3) << 16);
    lv.x = (uint32_t)__bfloat16_as_ushort(l0) | ((uint32_t)__bfloat16_as_ushort(l1) << 16);
    lv.y = (uint32_t)__bfloat16_as_ushort(l2) | ((uint32_t)__bfloat16_as_ushort(l3) << 16);
    *(uint2*)(aggh + (size_t)node * DD + lo4) = hv;
    *(uint2*)(aggl + (size_t)node * DD + lo4) = lv;
}

// ---------------- HMMA GEMM with cp.async + ldmatrix ------------------------
// out[m][j] = sum_k A[m][k]*B[j][k] + bias[j];  A = [mean | xin] bf16 hi/lo.
// CTA 128x128; K=256 in 4 chunks of 64; 8 warps (4m x 2n), warp tile 32x64.

#define GS_BIAS 0
#define GS_BH   512
#define GS_BL   (GS_BH + 65536)
#define GS_A    (GS_BL + 65536)
#define GS_STG  32768               // per A stage: hi 16K + lo 16K
#define GS_TOTAL (GS_A + 2 * GS_STG)

__global__ __launch_bounds__(256) void gemm_hmma_kernel(
    const ushort_t* __restrict__ mh, const ushort_t* __restrict__ ml,
    const ushort_t* __restrict__ xh, const ushort_t* __restrict__ xl,
    const ushort_t* __restrict__ Bh, const ushort_t* __restrict__ Bl,
    const float* __restrict__ bias,
    ushort_t* __restrict__ oh, ushort_t* __restrict__ ol,
    float* __restrict__ of, int n, int relu_bf16)
{
    extern __shared__ char smem[];
    const uint32_t sb = smem_u32(smem);
    float* bsh = (float*)(smem + GS_BIAS);

    const int tid  = threadIdx.x;
    const int lane = tid & 31;
    const int wid  = tid >> 5;
    const int brow = blockIdx.x * 128;
    const int m0 = (wid & 3) * 32;
    const int n0 = (wid >> 2) * 64;
    const int g  = lane >> 2;
    const int c2 = (lane & 3) * 2;

    if (tid < 128) bsh[tid] = bias[tid];

    const int lrow = tid >> 1;       // loader row 0..127
    const int half = tid & 1;
    const int grow = brow + lrow;
    const bool rok = (grow < n);
    const int growc = rok ? grow : (n - 1);

    // B: full 128x256 hi+lo via cp.async (rows 512B)
    {
        #pragma unroll
        for (int i = 0; i < 16; i++) {
            int kb = half * 256 + i * 16;      // byte offset within 512B row
            uint32_t dh = sb + GS_BH + BSWZ(lrow, kb);
            uint32_t dl = sb + GS_BL + BSWZ(lrow, kb);
            cp16(dh, (const char*)(Bh + lrow * 256) + kb, true);
            cp16(dl, (const char*)(Bl + lrow * 256) + kb, true);
        }
    }
    cp_commit();

    auto cpA = [&](int c) {
        int s = c & 1;
        const ushort_t* hs = (c < 2) ? mh : xh;
        const ushort_t* ls = (c < 2) ? ml : xl;
        int koff = (c & 1) * 64;
        const char* hp = (const char*)(hs + (size_t)growc * DD + koff);
        const char* lp = (const char*)(ls + (size_t)growc * DD + koff);
        uint32_t dst = sb + GS_A + s * GS_STG;
        #pragma unroll
        for (int i = 0; i < 4; i++) {
            int kb = half * 64 + i * 16;       // byte within 128B row
            cp16(dst + ASWZ(lrow, kb), hp + kb, rok);
            cp16(dst + 16384 + ASWZ(lrow, kb), lp + kb, rok);
        }
    };

    cpA(0); cp_commit();
    cpA(1); cp_commit();

    float acc[2][8][4];
    #pragma unroll
    for (int mi = 0; mi < 2; mi++)
        #pragma unroll
        for (int ni = 0; ni < 8; ni++)
            #pragma unroll
            for (int q = 0; q < 4; q++) acc[mi][ni][q] = 0.0f;

    cp_wait<1>();          // B + A0 complete
    __syncthreads();

    const int lr = lane & 15;
    const int lc = lane >> 4;
    const int br = (lane & 7) + ((lane >> 4) << 3);
    const int bc = ((lane >> 3) & 1) << 4;

    #pragma unroll
    for (int c = 0; c < 4; c++) {
        const uint32_t abase = sb + GS_A + (c & 1) * GS_STG;
        #pragma unroll
        for (int ks = 0; ks < 4; ks++) {
            uint32_t ah[2][4], al[2][4];
            #pragma unroll
            for (int mi = 0; mi < 2; mi++) {
                uint32_t addr = abase + ASWZ(m0 + mi * 16 + lr, ks * 32 + lc * 16);
                ldsm4(ah[mi], addr);
                ldsm4(al[mi], addr + 16384);
            }
            #pragma unroll
            for (int np = 0; np < 4; np++) {
                int rr = n0 + np * 16 + br;
                int kb = c * 128 + ks * 32 + bc;
                uint32_t bh4[4], bl4[4];
                uint32_t baddr = sb + GS_BH + BSWZ(rr, kb);
                ldsm4(bh4, baddr);
                ldsm4(bl4, baddr + 65536);
                #pragma unroll
                for (int mi = 0; mi < 2; mi++) {
                    mma16816(acc[mi][2 * np],     ah[mi], bh4[0], bh4[1]);
                    mma16816(acc[mi][2 * np],     ah[mi], bl4[0], bl4[1]);
                    mma16816(acc[mi][2 * np],     al[mi], bh4[0], bh4[1]);
                    mma16816(acc[mi][2 * np + 1], ah[mi], bh4[2], bh4[3]);
                    mma16816(acc[mi][2 * np + 1], ah[mi], bl4[2], bl4[3]);
                    mma16816(acc[mi][2 * np + 1], al[mi], bh4[2], bh4[3]);
                }
            }
        }
        if (c < 3) {
            __syncthreads();
            if (c < 2) { cpA(c + 2); cp_commit(); }
            if (c < 2) cp_wait<1>(); else cp_wait<0>();
            __syncthreads();
        }
    }

    // epilogue
    #pragma unroll
    for (int mi = 0; mi < 2; mi++) {
        int r0 = brow + m0 + mi * 16 + g;
        #pragma unroll
        for (int ni = 0; ni < 8; ni++) {
            int colx = n0 + ni * 8 + c2;
            float b0 = bsh[colx], b1 = bsh[colx + 1];
            float v0 = acc[mi][ni][0] + b0, v1 = acc[mi][ni][1] + b1;
            float v2 = acc[mi][ni][2] + b0, v3 = acc[mi][ni][3] + b1;
            if (relu_bf16) {
                v0 = fmaxf(v0, 0.f); v1 = fmaxf(v1, 0.f);
                v2 = fmaxf(v2, 0.f); v3 = fmaxf(v3, 0.f);
                if (r0 < n) {
                    size_t p = (size_t)r0 * DD + colx;
                    __nv_bfloat16 h0 = __float2bfloat16_rn(v0);
                    __nv_bfloat16 h1 = __float2bfloat16_rn(v1);
                    __nv_bfloat16 q0 = __float2bfloat16_rn(v0 - __bfloat162float(h0));
                    __nv_bfloat16 q1 = __float2bfloat16_rn(v1 - __bfloat162float(h1));
                    *(uint32_t*)(oh + p) = (uint32_t)__bfloat16_as_ushort(h0) |
                                           ((uint32_t)__bfloat16_as_ushort(h1) << 16);
                    *(uint32_t*)(ol + p) = (uint32_t)__bfloat16_as_ushort(q0) |
                                           ((uint32_t)__bfloat16_as_ushort(q1) << 16);
                }
                if (r0 + 8 < n) {
                    size_t p = (size_t)(r0 + 8) * DD + colx;
                    __nv_bfloat16 h0 = __float2bfloat16_rn(v2);
                    __nv_bfloat16 h1 = __float2bfloat16_rn(v3);
                    __nv_bfloat16 q0 = __float2bfloat16_rn(v2 - __bfloat162float(h0));
                    __nv_bfloat16 q1 = __float2bfloat16_rn(v3 - __bfloat162float(h1));
                    *(uint32_t*)(oh + p) = (uint32_t)__bfloat16_as_ushort(h0) |
                                           ((uint32_t)__bfloat16_as_ushort(h1) << 16);
                    *(uint32_t*)(ol + p) = (uint32_t)__bfloat16_as_ushort(q0) |
                                           ((uint32_t)__bfloat16_as_ushort(q1) << 16);
                }
            } else {
                if (r0 < n)
                    *(float2*)(of + (size_t)r0 * DD + colx) = make_float2(v0, v1);
                if (r0 + 8 < n)
                    *(float2*)(of + (size_t)(r0 + 8) * DD + colx) = make_float2(v2, v3);
            }
        }
    }
}

// ---------------- cleanup (restore invariants for next replay) --------------
__global__ void cleanup_kernel(int* __restrict__ deg, int n) {
    int i = blockIdx.x * blockDim.x + threadIdx.x;
    if (i < n) deg[i] = 0;
    if (i == 0) g_ecur = 0;
}

// ---------------- host orchestration ---------------------------------------
extern "C" void kernel_launch(void* const* d_in, const int* in_sizes, int n_in,
                              void* d_out, int out_size) {
    const float* x   = (const float*)d_in[0];
    const void*  ei  = d_in[1];
    const float* Wl1 = (const float*)d_in[2];
    const float* Wr1 = (const float*)d_in[3];
    const float* b1  = (const float*)d_in[4];
    const float* Wl2 = (const float*)d_in[5];
    const float* Wr2 = (const float*)d_in[6];
    const float* b2  = (const float*)d_in[7];
    const float* Wl3 = (const float*)d_in[8];
    const float* Wr3 = (const float*)d_in[9];
    const float* b3  = (const float*)d_in[10];

    const int n = in_sizes[0] / DD;
    const int e = in_sizes[1] / 2;
    float* out = (float*)d_out;

    ushort_t *xh, *xl, *h1h, *h1l, *h2h, *h2l, *aggh, *aggl, *bh, *bl;
    float* inv;
    int *deg, *rps, *rpe, *cursor, *col;
    cudaGetSymbolAddress((void**)&xh,   g_xh);
    cudaGetSymbolAddress((void**)&xl,   g_xl);
    cudaGetSymbolAddress((void**)&h1h,  g_h1h);
    cudaGetSymbolAddress((void**)&h1l,  g_h1l);
    cudaGetSymbolAddress((void**)&h2h,  g_h2h);
    cudaGetSymbolAddress((void**)&h2l,  g_h2l);
    cudaGetSymbolAddress((void**)&aggh, g_aggh);
    cudaGetSymbolAddress((void**)&aggl, g_aggl);
    cudaGetSymbolAddress((void**)&bh,   g_Bh);
    cudaGetSymbolAddress((void**)&bl,   g_Bl);
    cudaGetSymbolAddress((void**)&inv,  g_inv);
    cudaGetSymbolAddress((void**)&deg,  g_deg);
    cudaGetSymbolAddress((void**)&rps,  g_rps);
    cudaGetSymbolAddress((void**)&rpe,  g_rpe);
    cudaGetSymbolAddress((void**)&cursor, g_cursor);
    cudaGetSymbolAddress((void**)&col,  g_col);

    cudaFuncSetAttribute(gemm_hmma_kernel,
                         cudaFuncAttributeMaxDynamicSharedMemorySize, GS_TOTAL);

    const int thr = 256;
    const int eb  = (e + thr - 1) / thr;
    const int scb = (n + 1023) / 1024;
    const int gab = (int)(((long long)n * 32 + thr - 1) / thr);
    const int gmb = (n + 127) / 128;
    const int clb = (n + thr - 1) / thr;

    // 1: hist + x conversion
    hist_conv_kernel<<<eb, thr>>>(ei, e, deg, x, xh, xl, n);
    // 2: segment assignment + weight conversion
    seg_kernel<<<scb + 3, thr>>>(deg, rps, rpe, cursor, inv, n, scb,
                                 Wl1, Wr1, Wl2, Wr2, Wl3, Wr3, bh, bl);
    // 3: fill CSR columns
    fill_kernel<<<eb, thr>>>(ei, e, n, cursor, col);
    // 4-9: three layers
    gather_kernel<<<gab, thr>>>(xh, xl, rps, rpe, col, inv, aggh, aggl, n);
    gemm_hmma_kernel<<<gmb, thr, GS_TOTAL>>>(aggh, aggl, xh, xl,
        bh + 0 * 128 * 256, bl + 0 * 128 * 256, b1, h1h, h1l, out, n, 1);
    gather_kernel<<<gab, thr>>>(h1h, h1l, rps, rpe, col, inv, aggh, aggl, n);
    gemm_hmma_kernel<<<gmb, thr, GS_TOTAL>>>(aggh, aggl, h1h, h1l,
        bh + 1 * 128 * 256, bl + 1 * 128 * 256, b2, h2h, h2l, out, n, 1);
    gather_kernel<<<gab, thr>>>(h2h, h2l, rps, rpe, col, inv, aggh, aggl, n);
    gemm_hmma_kernel<<<gmb, thr, GS_TOTAL>>>(aggh, aggl, h2h, h2l,
        bh + 2 * 128 * 256, bl + 2 * 128 * 256, b3, nullptr, nullptr, out, n, 0);
    // 10: restore invariants for next replay
    cleanup_kernel<<<clb, thr>>>(deg, n);
}

// round 11
// speedup vs baseline: 1.3411x; 1.0373x over previous
#include <cuda_runtime.h>
#include <cuda_bf16.h>
#include <cstdint>
#include <cstddef>

#define NN 100000
#define EE 1600000
#define DD 128

typedef unsigned short ushort_t;

// ---------------- scratch (device globals; no allocation allowed) ----------
__device__ ushort_t g_xh[(size_t)NN * DD];
__device__ ushort_t g_xl[(size_t)NN * DD];
__device__ float    g_h1f[(size_t)NN * DD];
__device__ float    g_h2f[(size_t)NN * DD];
__device__ ushort_t g_h1h[(size_t)NN * DD];
__device__ ushort_t g_h1l[(size_t)NN * DD];
__device__ ushort_t g_h2h[(size_t)NN * DD];
__device__ ushort_t g_h2l[(size_t)NN * DD];
__device__ ushort_t g_aggh[(size_t)NN * DD];
__device__ ushort_t g_aggl[(size_t)NN * DD];
__device__ float    g_inv[NN];
__device__ __align__(16) ushort_t g_Bh[3][128 * 256];
__device__ __align__(16) ushort_t g_Bl[3][128 * 256];
__device__ int      g_deg[NN];
__device__ int      g_rps[NN];
__device__ int      g_rpe[NN];
__device__ int      g_cursor[NN];
__device__ int      g_col[EE];
__device__ int      g_ecur;

// ---------------- PTX helpers ----------------------------------------------
__device__ __forceinline__ uint32_t smem_u32(const void* p) {
    uint32_t a;
    asm("{ .reg .u64 t; cvta.to.shared.u64 t, %1; cvt.u32.u64 %0, t; }" : "=r"(a) : "l"(p));
    return a;
}
__device__ __forceinline__ void cp16(uint32_t dst, const void* src, bool ok) {
    int sz = ok ? 16 : 0;
    asm volatile("cp.async.cg.shared.global [%0], [%1], 16, %2;"
                 :: "r"(dst), "l"(src), "r"(sz));
}
__device__ __forceinline__ void cp_commit() {
    asm volatile("cp.async.commit_group;" ::: "memory");
}
template <int N>
__device__ __forceinline__ void cp_wait() {
    asm volatile("cp.async.wait_group %0;" :: "n"(N) : "memory");
}
__device__ __forceinline__ void ldsm4(uint32_t* r, uint32_t addr) {
    asm volatile("ldmatrix.sync.aligned.m8n8.x4.shared.b16 {%0,%1,%2,%3}, [%4];"
                 : "=r"(r[0]), "=r"(r[1]), "=r"(r[2]), "=r"(r[3]) : "r"(addr));
}
__device__ __forceinline__ void mma16816(float* d, const uint32_t* a,
                                         uint32_t b0, uint32_t b1) {
    asm volatile("mma.sync.aligned.m16n8k16.row.col.f32.bf16.bf16.f32 "
                 "{%0,%1,%2,%3}, {%4,%5,%6,%7}, {%8,%9}, {%0,%1,%2,%3};"
                 : "+f"(d[0]), "+f"(d[1]), "+f"(d[2]), "+f"(d[3])
                 : "r"(a[0]), "r"(a[1]), "r"(a[2]), "r"(a[3]), "r"(b0), "r"(b1));
}
// A smem: 128 rows x 128B (64 bf16); B smem: 128 rows x 512B (256 bf16)
__device__ __forceinline__ uint32_t ASWZ(int row, int kbyte) {
    return (uint32_t)(row * 128 + ((((kbyte >> 4) ^ (row & 7)) << 4) | (kbyte & 15)));
}
__device__ __forceinline__ uint32_t BSWZ(int row, int kbyte) {
    return (uint32_t)(row * 512 + (((((kbyte >> 4) & 7) ^ (row & 7)) << 4) |
                                   ((kbyte >> 4) & ~7) * 16 + (kbyte & 15)));
}

// per-block int64/int32 detection (warp 0 vote)
__device__ __forceinline__ int detect_is64(const void* ei, int e, int n, int* s_flag) {
    if (threadIdx.x < 32) {
        int ok = 1;
        int lim = (e < 256) ? e : 256;
        for (int q = threadIdx.x; q < lim; q += 32) {
            long long v = ((const long long*)ei)[q];
            if (v < 0 || v >= n) ok = 0;
        }
        int all = __all_sync(0xFFFFFFFFu, ok);
        if (threadIdx.x == 0) *s_flag = all;
    }
    __syncthreads();
    return *s_flag;
}
__device__ __forceinline__ int load_idx(const void* ei, int e, int i, int part, int is64) {
    if (is64) return (int)(((const long long*)ei)[(size_t)part * e + i]);
    return ((const int*)ei)[(size_t)part * e + i];
}

// ---------------- hist + x->bf16 hi/lo conversion ---------------------------
__global__ __launch_bounds__(256) void hist_conv_kernel(
    const void* __restrict__ ei, int e, int* __restrict__ deg,
    const float* __restrict__ x, ushort_t* __restrict__ xh, ushort_t* __restrict__ xl,
    int n)
{
    __shared__ int s64;
    int is64 = detect_is64(ei, e, n, &s64);
    int gid = blockIdx.x * blockDim.x + threadIdx.x;
    if (gid < e) {
        int dst = load_idx(ei, e, gid, 1, is64);
        atomicAdd(&deg[dst], 1);
    }
    size_t total = (size_t)n * DD;
    size_t stride = (size_t)gridDim.x * blockDim.x * 8;
    for (size_t j = (size_t)gid * 8; j + 7 < total; j += stride) {
        float4 p0 = *(const float4*)(x + j);
        float4 p1 = *(const float4*)(x + j + 4);
        float vv[8] = {p0.x, p0.y, p0.z, p0.w, p1.x, p1.y, p1.z, p1.w};
        ushort_t hh[8], ll[8];
        #pragma unroll
        for (int q = 0; q < 8; q++) {
            __nv_bfloat16 h = __float2bfloat16_rn(vv[q]);
            __nv_bfloat16 l = __float2bfloat16_rn(vv[q] - __bfloat162float(h));
            hh[q] = __bfloat16_as_ushort(h);
            ll[q] = __bfloat16_as_ushort(l);
        }
        *(uint4*)(xh + j) = *(uint4*)hh;
        *(uint4*)(xl + j) = *(uint4*)ll;
    }
}

// ---------------- segment assignment (block scan + atomic base) + wb build --
__global__ __launch_bounds__(256) void seg_kernel(
    const int* __restrict__ deg, int* __restrict__ rps, int* __restrict__ rpe,
    int* __restrict__ cursor, float* __restrict__ inv, int n, int scan_blocks,
    const float* __restrict__ Wl1, const float* __restrict__ Wr1,
    const float* __restrict__ Wl2, const float* __restrict__ Wr2,
    const float* __restrict__ Wl3, const float* __restrict__ Wr3,
    ushort_t* __restrict__ Bh, ushort_t* __restrict__ Bl)
{
    if ((int)blockIdx.x >= scan_blocks) {
        int layer = blockIdx.x - scan_blocks;
        const float* Wl = (layer == 0) ? Wl1 : (layer == 1) ? Wl2 : Wl3;
        const float* Wr = (layer == 0) ? Wr1 : (layer == 1) ? Wr2 : Wr3;
        ushort_t* bh = Bh + layer * 128 * 256;
        ushort_t* bl = Bl + layer * 128 * 256;
        for (int idx = threadIdx.x; idx < 128 * 256; idx += 256) {
            int j = idx >> 8, k = idx & 255;
            float w = (k < DD) ? Wl[j * DD + k] : Wr[j * DD + (k - DD)];
            __nv_bfloat16 h = __float2bfloat16_rn(w);
            __nv_bfloat16 l = __float2bfloat16_rn(w - __bfloat162float(h));
            bh[idx] = __bfloat16_as_ushort(h);
            bl[idx] = __bfloat16_as_ushort(l);
        }
        return;
    }
    __shared__ int wsum[8];
    __shared__ int sbase;
    int t = threadIdx.x;
    int base = blockIdx.x * 1024;
    int idx = base + t * 4;
    int v[4];
    #pragma unroll
    for (int j = 0; j < 4; j++) v[j] = (idx + j < n) ? deg[idx + j] : 0;
    int tsum = v[0] + v[1] + v[2] + v[3];
    int lane = t & 31, w = t >> 5;
    int inc = tsum;
    #pragma unroll
    for (int d = 1; d < 32; d <<= 1) {
        int x2 = __shfl_up_sync(0xFFFFFFFFu, inc, d);
        if (lane >= d) inc += x2;
    }
    if (lane == 31) wsum[w] = inc;
    __syncthreads();
    if (t == 0) {
        int a = 0;
        #pragma unroll
        for (int i = 0; i < 8; i++) { int tmp = wsum[i]; wsum[i] = a; a += tmp; }
        sbase = atomicAdd(&g_ecur, a);
    }
    __syncthreads();
    int run = sbase + wsum[w] + (inc - tsum);
    #pragma unroll
    for (int j = 0; j < 4; j++) {
        if (idx + j < n) {
            rps[idx + j] = run;
            rpe[idx + j] = run + v[j];
            cursor[idx + j] = run;
            inv[idx + j] = 1.0f / fmaxf((float)v[j], 1.0f);
        }
        run += v[j];
    }
}

// ---------------- fill + invariants reset -----------------------------------
__global__ __launch_bounds__(256) void fill_kernel(
    const void* __restrict__ ei, int e, int n,
    int* __restrict__ cursor, int* __restrict__ col, int* __restrict__ deg)
{
    __shared__ int s64;
    int is64 = detect_is64(ei, e, n, &s64);
    int i = blockIdx.x * blockDim.x + threadIdx.x;
    if (i < n) deg[i] = 0;            // deg consumed by seg; re-zero for next replay
    if (i == 0) g_ecur = 0;
    if (i >= e) return;
    int src = load_idx(ei, e, i, 0, is64);
    int dst = load_idx(ei, e, i, 1, is64);
    int pos = atomicAdd(&cursor[dst], 1);
    col[pos] = src;
}

// ---------------- gather mean (fp32 in, bf16 hi/lo out) ---------------------
__global__ __launch_bounds__(256) void gather_kernel(
    const float* __restrict__ xf,
    const int* __restrict__ rps, const int* __restrict__ rpe,
    const int* __restrict__ col, const float* __restrict__ inv,
    ushort_t* __restrict__ aggh, ushort_t* __restrict__ aggl, int n)
{
    int node = (blockIdx.x * blockDim.x + threadIdx.x) >> 5;
    int lane = threadIdx.x & 31;
    if (node >= n) return;
    int beg = rps[node], end = rpe[node];
    const float4* xv = (const float4*)xf;
    float4 a0 = make_float4(0.f, 0.f, 0.f, 0.f);
    float4 a1 = a0;
    int j = beg;
    for (; j + 2 <= end; j += 2) {
        int s0 = __ldg(&col[j]);
        int s1 = __ldg(&col[j + 1]);
        float4 v0 = __ldg(&xv[(size_t)s0 * 32 + lane]);
        float4 v1 = __ldg(&xv[(size_t)s1 * 32 + lane]);
        a0.x += v0.x; a0.y += v0.y; a0.z += v0.z; a0.w += v0.w;
        a1.x += v1.x; a1.y += v1.y; a1.z += v1.z; a1.w += v1.w;
    }
    if (j < end) {
        int s = __ldg(&col[j]);
        float4 v = __ldg(&xv[(size_t)s * 32 + lane]);
        a0.x += v.x; a0.y += v.y; a0.z += v.z; a0.w += v.w;
    }
    float sc = inv[node];
    float f0 = (a0.x + a1.x) * sc;
    float f1 = (a0.y + a1.y) * sc;
    float f2 = (a0.z + a1.z) * sc;
    float f3 = (a0.w + a1.w) * sc;
    __nv_bfloat16 h0 = __float2bfloat16_rn(f0);
    __nv_bfloat16 h1 = __float2bfloat16_rn(f1);
    __nv_bfloat16 h2 = __float2bfloat16_rn(f2);
    __nv_bfloat16 h3 = __float2bfloat16_rn(f3);
    __nv_bfloat16 l0 = __float2bfloat16_rn(f0 - __bfloat162float(h0));
    __nv_bfloat16 l1 = __float2bfloat16_rn(f1 - __bfloat162float(h1));
    __nv_bfloat16 l2 = __float2bfloat16_rn(f2 - __bfloat162float(h2));
    __nv_bfloat16 l3 = __float2bfloat16_rn(f3 - __bfloat162float(h3));
    uint2 hv, lv;
    hv.x = (uint32_t)__bfloat16_as_ushort(h0) | ((uint32_t)__bfloat16_as_ushort(h1) << 16);
    hv.y = (uint32_t)__bfloat16_as_ushort(h2) | ((uint32_t)__bfloat16_as_ushort(h3) << 16);
    lv.x = (uint32_t)__bfloat16_as_ushort(l0) | ((uint32_t)__bfloat16_as_ushort(l1) << 16);
    lv.y = (uint32_t)__bfloat16_as_ushort(l2) | ((uint32_t)__bfloat16_as_ushort(l3) << 16);
    size_t lo4 = (size_t)lane * 4;
    *(uint2*)(aggh + (size_t)node * DD + lo4) = hv;
    *(uint2*)(aggl + (size_t)node * DD + lo4) = lv;
}

// ---------------- HMMA GEMM with cp.async + ldmatrix ------------------------
// out[m][j] = sum_k A[m][k]*B[j][k] + bias[j];  A = [mean | xin] bf16 hi/lo.
// CTA 128x128; K=256 in 4 chunks of 64; 8 warps (4m x 2n), warp tile 32x64.

#define GS_BIAS 0
#define GS_BH   512
#define GS_BL   (GS_BH + 65536)
#define GS_A    (GS_BL + 65536)
#define GS_STG  32768               // per A stage: hi 16K + lo 16K
#define GS_TOTAL (GS_A + 2 * GS_STG)

__global__ __launch_bounds__(256) void gemm_hmma_kernel(
    const ushort_t* __restrict__ mh, const ushort_t* __restrict__ ml,
    const ushort_t* __restrict__ xh, const ushort_t* __restrict__ xl,
    const ushort_t* __restrict__ Bh, const ushort_t* __restrict__ Bl,
    const float* __restrict__ bias,
    ushort_t* __restrict__ oh, ushort_t* __restrict__ ol,
    float* __restrict__ of, int n, int relu_split)
{
    extern __shared__ char smem[];
    const uint32_t sb = smem_u32(smem);
    float* bsh = (float*)(smem + GS_BIAS);

    const int tid  = threadIdx.x;
    const int lane = tid & 31;
    const int wid  = tid >> 5;
    const int brow = blockIdx.x * 128;
    const int m0 = (wid & 3) * 32;
    const int n0 = (wid >> 2) * 64;
    const int g  = lane >> 2;
    const int c2 = (lane & 3) * 2;

    if (tid < 128) bsh[tid] = bias[tid];

    const int lrow = tid >> 1;       // loader row 0..127
    const int half = tid & 1;
    const int grow = brow + lrow;
    const bool rok = (grow < n);
    const int growc = rok ? grow : (n - 1);

    // B: full 128x256 hi+lo via cp.async (rows 512B)
    {
        #pragma unroll
        for (int i = 0; i < 16; i++) {
            int kb = half * 256 + i * 16;      // byte offset within 512B row
            uint32_t dh = sb + GS_BH + BSWZ(lrow, kb);
            uint32_t dl = sb + GS_BL + BSWZ(lrow, kb);
            cp16(dh, (const char*)(Bh + lrow * 256) + kb, true);
            cp16(dl, (const char*)(Bl + lrow * 256) + kb, true);
        }
    }
    cp_commit();

    auto cpA = [&](int c) {
        int s = c & 1;
        const ushort_t* hs = (c < 2) ? mh : xh;
        const ushort_t* ls = (c < 2) ? ml : xl;
        int koff = (c & 1) * 64;
        const char* hp = (const char*)(hs + (size_t)growc * DD + koff);
        const char* lp = (const char*)(ls + (size_t)growc * DD + koff);
        uint32_t dst = sb + GS_A + s * GS_STG;
        #pragma unroll
        for (int i = 0; i < 4; i++) {
            int kb = half * 64 + i * 16;       // byte within 128B row
            cp16(dst + ASWZ(lrow, kb), hp + kb, rok);
            cp16(dst + 16384 + ASWZ(lrow, kb), lp + kb, rok);
        }
    };

    cpA(0); cp_commit();
    cpA(1); cp_commit();

    float acc[2][8][4];
    #pragma unroll
    for (int mi = 0; mi < 2; mi++)
        #pragma unroll
        for (int ni = 0; ni < 8; ni++)
            #pragma unroll
            for (int q = 0; q < 4; q++) acc[mi][ni][q] = 0.0f;

    cp_wait<1>();          // B + A0 complete
    __syncthreads();

    const int lr = lane & 15;
    const int lc = lane >> 4;
    const int br = (lane & 7) + ((lane >> 4) << 3);
    const int bc = ((lane >> 3) & 1) << 4;

    #pragma unroll
    for (int c = 0; c < 4; c++) {
        const uint32_t abase = sb + GS_A + (c & 1) * GS_STG;
        #pragma unroll
        for (int ks = 0; ks < 4; ks++) {
            uint32_t ah[2][4], al[2][4];
            #pragma unroll
            for (int mi = 0; mi < 2; mi++) {
                uint32_t addr = abase + ASWZ(m0 + mi * 16 + lr, ks * 32 + lc * 16);
                ldsm4(ah[mi], addr);
                ldsm4(al[mi], addr + 16384);
            }
            #pragma unroll
            for (int np = 0; np < 4; np++) {
                int rr = n0 + np * 16 + br;
                int kb = c * 128 + ks * 32 + bc;
                uint32_t bh4[4], bl4[4];
                uint32_t baddr = sb + GS_BH + BSWZ(rr, kb);
                ldsm4(bh4, baddr);
                ldsm4(bl4, baddr + 65536);
                #pragma unroll
                for (int mi = 0; mi < 2; mi++) {
                    mma16816(acc[mi][2 * np],     ah[mi], bh4[0], bh4[1]);
                    mma16816(acc[mi][2 * np],     ah[mi], bl4[0], bl4[1]);
                    mma16816(acc[mi][2 * np],     al[mi], bh4[0], bh4[1]);
                    mma16816(acc[mi][2 * np + 1], ah[mi], bh4[2], bh4[3]);
                    mma16816(acc[mi][2 * np + 1], ah[mi], bl4[2], bl4[3]);
                    mma16816(acc[mi][2 * np + 1], al[mi], bh4[2], bh4[3]);
                }
            }
        }
        if (c < 3) {
            __syncthreads();
            if (c < 2) { cpA(c + 2); cp_commit(); }
            if (c < 2) cp_wait<1>(); else cp_wait<0>();
            __syncthreads();
        }
    }

    // epilogue
    #pragma unroll
    for (int mi = 0; mi < 2; mi++) {
        int r0 = brow + m0 + mi * 16 + g;
        #pragma unroll
        for (int ni = 0; ni < 8; ni++) {
            int colx = n0 + ni * 8 + c2;
            float b0 = bsh[colx], b1 = bsh[colx + 1];
            float v0 = acc[mi][ni][0] + b0, v1 = acc[mi][ni][1] + b1;
            float v2 = acc[mi][ni][2] + b0, v3 = acc[mi][ni][3] + b1;
            if (relu_split) {
                v0 = fmaxf(v0, 0.f); v1 = fmaxf(v1, 0.f);
                v2 = fmaxf(v2, 0.f); v3 = fmaxf(v3, 0.f);
                if (r0 < n) {
                    size_t p = (size_t)r0 * DD + colx;
                    *(float2*)(of + p) = make_float2(v0, v1);
                    __nv_bfloat16 h0 = __float2bfloat16_rn(v0);
                    __nv_bfloat16 h1 = __float2bfloat16_rn(v1);
                    __nv_bfloat16 q0 = __float2bfloat16_rn(v0 - __bfloat162float(h0));
                    __nv_bfloat16 q1 = __float2bfloat16_rn(v1 - __bfloat162float(h1));
                    *(uint32_t*)(oh + p) = (uint32_t)__bfloat16_as_ushort(h0) |
                                           ((uint32_t)__bfloat16_as_ushort(h1) << 16);
                    *(uint32_t*)(ol + p) = (uint32_t)__bfloat16_as_ushort(q0) |
                                           ((uint32_t)__bfloat16_as_ushort(q1) << 16);
                }
                if (r0 + 8 < n) {
                    size_t p = (size_t)(r0 + 8) * DD + colx;
                    *(float2*)(of + p) = make_float2(v2, v3);
                    __nv_bfloat16 h0 = __float2bfloat16_rn(v2);
                    __nv_bfloat16 h1 = __float2bfloat16_rn(v3);
                    __nv_bfloat16 q0 = __float2bfloat16_rn(v2 - __bfloat162float(h0));
                    __nv_bfloat16 q1 = __float2bfloat16_rn(v3 - __bfloat162float(h1));
                    *(uint32_t*)(oh + p) = (uint32_t)__bfloat16_as_ushort(h0) |
                                           ((uint32_t)__bfloat16_as_ushort(h1) << 16);
                    *(uint32_t*)(ol + p) = (uint32_t)__bfloat16_as_ushort(q0) |
                                           ((uint32_t)__bfloat16_as_ushort(q1) << 16);
                }
            } else {
                if (r0 < n)
                    *(float2*)(of + (size_t)r0 * DD + colx) = make_float2(v0, v1);
                if (r0 + 8 < n)
                    *(float2*)(of + (size_t)(r0 + 8) * DD + colx) = make_float2(v2, v3);
            }
        }
    }
}

// ---------------- host orchestration ---------------------------------------
extern "C" void kernel_launch(void* const* d_in, const int* in_sizes, int n_in,
                              void* d_out, int out_size) {
    const float* x   = (const float*)d_in[0];
    const void*  ei  = d_in[1];
    const float* Wl1 = (const float*)d_in[2];
    const float* Wr1 = (const float*)d_in[3];
    const float* b1  = (const float*)d_in[4];
    const float* Wl2 = (const float*)d_in[5];
    const float* Wr2 = (const float*)d_in[6];
    const float* b2  = (const float*)d_in[7];
    const float* Wl3 = (const float*)d_in[8];
    const float* Wr3 = (const float*)d_in[9];
    const float* b3  = (const float*)d_in[10];

    const int n = in_sizes[0] / DD;
    const int e = in_sizes[1] / 2;
    float* out = (float*)d_out;

    ushort_t *xh, *xl, *h1h, *h1l, *h2h, *h2l, *aggh, *aggl, *bh, *bl;
    float *h1f, *h2f, *inv;
    int *deg, *rps, *rpe, *cursor, *col;
    cudaGetSymbolAddress((void**)&xh,   g_xh);
    cudaGetSymbolAddress((void**)&xl,   g_xl);
    cudaGetSymbolAddress((void**)&h1f,  g_h1f);
    cudaGetSymbolAddress((void**)&h2f,  g_h2f);
    cudaGetSymbolAddress((void**)&h1h,  g_h1h);
    cudaGetSymbolAddress((void**)&h1l,  g_h1l);
    cudaGetSymbolAddress((void**)&h2h,  g_h2h);
    cudaGetSymbolAddress((void**)&h2l,  g_h2l);
    cudaGetSymbolAddress((void**)&aggh, g_aggh);
    cudaGetSymbolAddress((void**)&aggl, g_aggl);
    cudaGetSymbolAddress((void**)&bh,   g_Bh);
    cudaGetSymbolAddress((void**)&bl,   g_Bl);
    cudaGetSymbolAddress((void**)&inv,  g_inv);
    cudaGetSymbolAddress((void**)&deg,  g_deg);
    cudaGetSymbolAddress((void**)&rps,  g_rps);
    cudaGetSymbolAddress((void**)&rpe,  g_rpe);
    cudaGetSymbolAddress((void**)&cursor, g_cursor);
    cudaGetSymbolAddress((void**)&col,  g_col);

    cudaFuncSetAttribute(gemm_hmma_kernel,
                         cudaFuncAttributeMaxDynamicSharedMemorySize, GS_TOTAL);

    const int thr = 256;
    const int eb  = (e + thr - 1) / thr;
    const int scb = (n + 1023) / 1024;
    const int gab = (int)(((long long)n * 32 + thr - 1) / thr);
    const int gmb = (n + 127) / 128;

    // 1: hist + x conversion
    hist_conv_kernel<<<eb, thr>>>(ei, e, deg, x, xh, xl, n);
    // 2: segment assignment + weight conversion
    seg_kernel<<<scb + 3, thr>>>(deg, rps, rpe, cursor, inv, n, scb,
                                 Wl1, Wr1, Wl2, Wr2, Wl3, Wr3, bh, bl);
    // 3: fill CSR columns (+ reset invariants for next replay)
    fill_kernel<<<eb, thr>>>(ei, e, n, cursor, col, deg);
    // 4-9: three layers
    gather_kernel<<<gab, thr>>>(x, rps, rpe, col, inv, aggh, aggl, n);
    gemm_hmma_kernel<<<gmb, thr, GS_TOTAL>>>(aggh, aggl, xh, xl,
        bh + 0 * 128 * 256, bl + 0 * 128 * 256, b1, h1h, h1l, h1f, n, 1);
    gather_kernel<<<gab, thr>>>(h1f, rps, rpe, col, inv, aggh, aggl, n);
    gemm_hmma_kernel<<<gmb, thr, GS_TOTAL>>>(aggh, aggl, h1h, h1l,
        bh + 1 * 128 * 256, bl + 1 * 128 * 256, b2, h2h, h2l, h2f, n, 1);
    gather_kernel<<<gab, thr>>>(h2f, rps, rpe, col, inv, aggh, aggl, n);
    gemm_hmma_kernel<<<gmb, thr, GS_TOTAL>>>(aggh, aggl, h2h, h2l,
        bh + 2 * 128 * 256, bl + 2 * 128 * 256, b3, nullptr, nullptr, out, n, 0);
}